// round 1
// baseline (speedup 1.0000x reference)
#include <cuda_runtime.h>

// Problem constants (fixed by setup_inputs)
#define BB      4
#define IN_DIM  8
#define OUT_DIM 64
#define N_WIN   64
#define N_SEQ   4096
#define N_REAL  6144

typedef unsigned long long ull;

// Scratch (no allocation allowed): z duplicated pairs (z,z), and weight pairs (W[o],W[o+32])
__device__ float2 g_zdup[BB * IN_DIM * N_REAL];      // 1.5 MB
__device__ float2 g_wpair[IN_DIM * N_WIN * 32];      // 128 KB

// ---------------- prep kernels ----------------

__global__ void zero_kernel() {
    int idx = blockIdx.x * blockDim.x + threadIdx.x;
    if (idx < BB * IN_DIM * N_REAL) g_zdup[idx] = make_float2(0.f, 0.f);
}

__global__ void scatter_kernel(const float* __restrict__ x, const int* __restrict__ srcIdx) {
    int g = blockIdx.x * blockDim.x + threadIdx.x;  // B*N_SEQ = 16384
    if (g >= BB * N_SEQ) return;
    int b = g / N_SEQ, s = g % N_SEQ;
    int t = srcIdx[b * N_SEQ + s];                  // sorted, unique, in [0, N_REAL)
#pragma unroll
    for (int i = 0; i < IN_DIM; i++) {
        float v = x[(b * IN_DIM + i) * N_SEQ + s];
        g_zdup[(b * IN_DIM + i) * N_REAL + t] = make_float2(v, v);
    }
}

__global__ void wprep_kernel(const float* __restrict__ w) {
    int g = blockIdx.x * blockDim.x + threadIdx.x;  // IN_DIM*N_WIN*32 = 16384
    if (g >= IN_DIM * N_WIN * 32) return;
    int lane = g & 31;
    int wi = (g >> 5) & (N_WIN - 1);
    int i = g >> 11;
    float a = w[(lane)      * IN_DIM * N_WIN + i * N_WIN + wi];
    float c = w[(lane + 32) * IN_DIM * N_WIN + i * N_WIN + wi];
    g_wpair[g] = make_float2(a, c);
}

// ---------------- main conv kernel ----------------

__device__ __forceinline__ ull ffma2(ull a, ull b, ull c) {
    ull d;
    asm("fma.rn.f32x2 %0, %1, %2, %3;" : "=l"(d) : "l"(a), "l"(b), "l"(c));
    return d;
}

__device__ __forceinline__ ull pack2(float x, float y) {
    ull r;
    asm("mov.b64 %0, {%1, %2};" : "=l"(r) : "f"(x), "f"(y));
    return r;
}

__device__ __forceinline__ void unpack2(ull v, float& x, float& y) {
    asm("mov.b64 {%0, %1}, %2;" : "=f"(x), "=f"(y) : "l"(v));
}

#define T_BLK 64   // t-tile per block; 8 warps x 8 t each

__global__ __launch_bounds__(256)
void conv_kernel(const float* __restrict__ bias, float* __restrict__ out) {
    __shared__ ull   zs[IN_DIM * 128];          // z tile (dup pairs), local t = global t - t0 + 63
    __shared__ float outtile[OUT_DIM * 65];     // padded for conflict-free transpose

    const int tid  = threadIdx.x;
    const int b    = blockIdx.x / (N_REAL / T_BLK);
    const int tile = blockIdx.x % (N_REAL / T_BLK);
    const int t0   = tile * T_BLK;

    // Stage z tile: local index k in [0,128) maps to global t = t0 - 63 + k
    const ull* zg = (const ull*)g_zdup;
#pragma unroll
    for (int p = 0; p < 4; p++) {
        int idx = tid + p * 256;                // 0..1023 = 8 rows x 128
        int i = idx >> 7;
        int k = idx & 127;
        int t = t0 - 63 + k;
        ull v = 0ULL;
        if (t >= 0 && t < N_REAL) v = zg[(b * IN_DIM + i) * N_REAL + t];
        zs[idx] = v;
    }
    __syncthreads();

    const int wid  = tid >> 5;                  // warp handles t in [t0 + 8*wid, t0 + 8*wid + 8)
    const int lane = tid & 31;                  // lane handles channel pair (lane, lane+32)

    ull acc[8];
    {
        ull bpack = pack2(bias[lane], bias[lane + 32]);
#pragma unroll
        for (int j = 0; j < 8; j++) acc[j] = bpack;
    }

    const ull* wbase = (const ull*)g_wpair + lane;

#pragma unroll 1
    for (int i = 0; i < IN_DIM; i++) {
        // zs row pointer, positioned so (zrow - w0)[k] == z[t0 + wid*8 + (k - 7) ... ] window
        const ull* zrow = zs + i * 128 + (wid * 8 + 56);
        const ull* wrow = wbase + i * (N_WIN * 32);

#pragma unroll 1
        for (int w0 = 0; w0 < N_WIN; w0 += 8) {
            // Window of 16 dup-pairs covering lags [w0, w0+8) for 8 outputs j
            ull zw[16];
            const ulonglong2* zp = (const ulonglong2*)(zrow - w0);  // 16B aligned
#pragma unroll
            for (int k2 = 0; k2 < 8; k2++) {
                ulonglong2 v = zp[k2];
                zw[2 * k2] = v.x;
                zw[2 * k2 + 1] = v.y;
            }
            // Prefetch 8 weight pairs (coalesced LDG64, L1-resident)
            ull wt[8];
#pragma unroll
            for (int w = 0; w < 8; w++) wt[w] = wrow[(w0 + w) * 32];

#pragma unroll
            for (int w = 0; w < 8; w++) {
#pragma unroll
                for (int j = 0; j < 8; j++) {
                    // zw[j+7-w] == z[(t0 + wid*8 + j) - (w0 + w)]
                    acc[j] = ffma2(zw[j + 7 - w], wt[w], acc[j]);
                }
            }
        }
    }

    // Transpose through smem so global stores are coalesced along t
#pragma unroll
    for (int j = 0; j < 8; j++) {
        float lo, hi;
        unpack2(acc[j], lo, hi);
        int lt = wid * 8 + j;
        outtile[lane * 65 + lt]        = lo;
        outtile[(lane + 32) * 65 + lt] = hi;
    }
    __syncthreads();

#pragma unroll
    for (int r = 0; r < 16; r++) {
        int linear = tid + r * 256;             // 0..4095 = 64 o x 64 t
        int o = linear >> 6;
        int t = linear & 63;
        out[(b * OUT_DIM + o) * N_REAL + t0 + t] = outtile[o * 65 + t];
    }
}

// ---------------- launch ----------------

extern "C" void kernel_launch(void* const* d_in, const int* in_sizes, int n_in,
                              void* d_out, int out_size) {
    const float* x      = (const float*)d_in[0];   // (4, 8, 4096)
    const float* weight = (const float*)d_in[1];   // (64, 8, 64)
    const float* bias   = (const float*)d_in[2];   // (64,)
    const int*   srcIdx = (const int*)d_in[3];     // (4, 4096)
    float*       out    = (float*)d_out;           // (4, 64, 6144)

    zero_kernel<<<(BB * IN_DIM * N_REAL + 255) / 256, 256>>>();
    scatter_kernel<<<(BB * N_SEQ + 255) / 256, 256>>>(x, srcIdx);
    wprep_kernel<<<(IN_DIM * N_WIN * 32 + 255) / 256, 256>>>(weight);
    conv_kernel<<<BB * (N_REAL / T_BLK), 256>>>(bias, out);
}